// round 13
// baseline (speedup 1.0000x reference)
#include <cuda_runtime.h>
#include <cuda_bf16.h>

#define NMAX 100000
#define NPAD 100128          // NMAX rounded up to 128-row block
#define EMAX 1600000
#define DEGMAX 64

// ---------------- scratch (device globals) -----------------------------------
__device__ int      g_cnt[NMAX];
__device__ float    g_dinv[NMAX];
__device__ int      g_srcfix[(size_t)NMAX * DEGMAX];  // per-dst src lists
__device__ float    g_h1[(size_t)NPAD * 64];          // UNscaled layer1 features
__device__ unsigned g_a1h[(size_t)NPAD * 32];         // a1 bf16-hi packed pairs
__device__ unsigned g_a1l[(size_t)NPAD * 32];         // a1 bf16-lo packed pairs
__device__ float    g_h2[(size_t)NPAD * 32];          // dinv-scaled layer2 features
__device__ uint4    g_wfrag[4096];                    // W1 bf16 fragments
__device__ uint4    g_w2frag[512];                    // W2 bf16 fragments

// ---------------- bf16 helpers -------------------------------------------------
__device__ __forceinline__ unsigned pack_bf16(__nv_bfloat16 lo, __nv_bfloat16 hi) {
    __nv_bfloat162 p; p.x = lo; p.y = hi;
    return *(unsigned*)&p;
}
__device__ __forceinline__ void split_bf16(float f, __nv_bfloat16& h, __nv_bfloat16& l) {
    h = __float2bfloat16_rn(f);
    l = __float2bfloat16_rn(f - __bfloat162float(h));
}
__device__ __forceinline__ void mma_bf16(float* d, const unsigned* a, unsigned b0, unsigned b1) {
    asm volatile(
        "mma.sync.aligned.m16n8k16.row.col.f32.bf16.bf16.f32 "
        "{%0,%1,%2,%3}, {%4,%5,%6,%7}, {%8,%9}, {%0,%1,%2,%3};"
        : "+f"(d[0]), "+f"(d[1]), "+f"(d[2]), "+f"(d[3])
        : "r"(a[0]), "r"(a[1]), "r"(a[2]), "r"(a[3]), "r"(b0), "r"(b1));
}

// ---- prep: W1/W2 bf16 hi/lo fragments (validated layouts) ----------------------
__global__ void k_prepw(const float* __restrict__ W1, const float* __restrict__ W2) {
    int i = blockIdx.x * blockDim.x + threadIdx.x;
    if (i < 4096) {   // W1 fragments
        int lane = i & 31;
        int t    = (i >> 5) & 7;
        int ks   = i >> 8;
        int qid = lane & 3, grp = lane >> 2;
        int col = t * 8 + grp;
        int k0 = ks * 16 + qid * 2;
        float f00 = W1[k0 * 64 + col],       f01 = W1[(k0 + 1) * 64 + col];
        float f10 = W1[(k0 + 8) * 64 + col], f11 = W1[(k0 + 9) * 64 + col];
        __nv_bfloat16 h00, l00, h01, l01, h10, l10, h11, l11;
        split_bf16(f00, h00, l00); split_bf16(f01, h01, l01);
        split_bf16(f10, h10, l10); split_bf16(f11, h11, l11);
        g_wfrag[i] = make_uint4(pack_bf16(h00, h01), pack_bf16(h10, h11),
                                pack_bf16(l00, l01), pack_bf16(l10, l11));
    }
    if (i < 512) {    // W2 fragments
        int lane = i & 31;
        int t    = (i >> 5) & 3;
        int ks   = i >> 7;
        int qid = lane & 3, grp = lane >> 2;
        int col = t * 8 + grp;
        int k0 = ks * 16 + qid * 2;
        float f00 = W2[k0 * 32 + col],       f01 = W2[(k0 + 1) * 32 + col];
        float f10 = W2[(k0 + 8) * 32 + col], f11 = W2[(k0 + 9) * 32 + col];
        __nv_bfloat16 h00, l00, h01, l01, h10, l10, h11, l11;
        split_bf16(f00, h00, l00); split_bf16(f01, h01, l01);
        split_bf16(f10, h10, l10); split_bf16(f11, h11, l11);
        g_w2frag[i] = make_uint4(pack_bf16(h00, h01), pack_bf16(h10, h11),
                                 pack_bf16(l00, l01), pack_bf16(l10, l11));
    }
}

__global__ void k_dinv(int n) {
    int i = blockIdx.x * blockDim.x + threadIdx.x;
    if (i < n) g_dinv[i] = rsqrtf((float)(g_cnt[i] + 1));  // +1 self loop
}

// ---- MEGA: gemm1 tiles (blocks < g1) + edge-bucket fill (blocks >= g1) --------
// gemm1: R12 ping-pong form, UNscaled output (no dinv dependency!).
// fill: atomicAdd degree + scatter src into fixed-stride buckets. The fill blocks
// backfill idle issue slots of the latency-bound gemm blocks — free concurrency.
#define XS2 20
__global__ __launch_bounds__(256) void k_mega(const float* __restrict__ x, int n,
                                              const int* __restrict__ src,
                                              const int* __restrict__ dst, int e,
                                              int g1) {
    __shared__ unsigned xhi[2][64 * XS2];
    __shared__ unsigned xlo[2][64 * XS2];
    int tid = threadIdx.x;

    if (blockIdx.x >= g1) {            // ---------- fill path ----------
        int i = (blockIdx.x - g1) * 256 + tid;
        if (i < e) {
            int s = src[i], d = dst[i];
            int pos = atomicAdd(&g_cnt[d], 1);
            if (pos < DEGMAX) g_srcfix[(size_t)d * DEGMAX + pos] = s;
        }
        return;
    }

    // ---------- gemm1 path (R12 double-buffered, proven) ----------
    int lane = tid & 31, warp = tid >> 5;
    int node0 = blockIdx.x * 64;
    int grp = lane >> 2, qid = lane & 3;
    int rg = warp >> 1, cg = warp & 1;

    float d[4][4];
#pragma unroll
    for (int t = 0; t < 4; t++) { d[t][0] = d[t][1] = d[t][2] = d[t][3] = 0.f; }

    int srow = tid >> 2;
    int sq   = tid & 3;
    bool srow_ok = (node0 + srow < n);
    const float4* xrow = (const float4*)(x + (size_t)(node0 + srow) * 256 + sq * 8);

    // stage chunk 0 into buffer 0
    {
        float4 v0 = make_float4(0.f, 0.f, 0.f, 0.f), v1 = v0;
        if (srow_ok) { v0 = xrow[0]; v1 = xrow[1]; }
        __nv_bfloat16 h0, l0, h1, l1;
        unsigned ph0, ph1, ph2, ph3, pl0, pl1, pl2, pl3;
        split_bf16(v0.x, h0, l0); split_bf16(v0.y, h1, l1);
        ph0 = pack_bf16(h0, h1); pl0 = pack_bf16(l0, l1);
        split_bf16(v0.z, h0, l0); split_bf16(v0.w, h1, l1);
        ph1 = pack_bf16(h0, h1); pl1 = pack_bf16(l0, l1);
        split_bf16(v1.x, h0, l0); split_bf16(v1.y, h1, l1);
        ph2 = pack_bf16(h0, h1); pl2 = pack_bf16(l0, l1);
        split_bf16(v1.z, h0, l0); split_bf16(v1.w, h1, l1);
        ph3 = pack_bf16(h0, h1); pl3 = pack_bf16(l0, l1);
        unsigned base = srow * XS2 + sq * 4;
        *(uint4*)(xhi[0] + base) = make_uint4(ph0, ph1, ph2, ph3);
        *(uint4*)(xlo[0] + base) = make_uint4(pl0, pl1, pl2, pl3);
    }

    for (int kc = 0; kc < 8; kc++) {
        __syncthreads();
        int buf = kc & 1;
        if (kc + 1 < 8) {
            float4 v0 = make_float4(0.f, 0.f, 0.f, 0.f), v1 = v0;
            if (srow_ok) {
                const float4* xp = xrow + (size_t)(kc + 1) * 8;
                v0 = xp[0]; v1 = xp[1];
            }
            __nv_bfloat16 h0, l0, h1, l1;
            unsigned ph0, ph1, ph2, ph3, pl0, pl1, pl2, pl3;
            split_bf16(v0.x, h0, l0); split_bf16(v0.y, h1, l1);
            ph0 = pack_bf16(h0, h1); pl0 = pack_bf16(l0, l1);
            split_bf16(v0.z, h0, l0); split_bf16(v0.w, h1, l1);
            ph1 = pack_bf16(h0, h1); pl1 = pack_bf16(l0, l1);
            split_bf16(v1.x, h0, l0); split_bf16(v1.y, h1, l1);
            ph2 = pack_bf16(h0, h1); pl2 = pack_bf16(l0, l1);
            split_bf16(v1.z, h0, l0); split_bf16(v1.w, h1, l1);
            ph3 = pack_bf16(h0, h1); pl3 = pack_bf16(l0, l1);
            unsigned base = srow * XS2 + sq * 4;
            *(uint4*)(xhi[buf ^ 1] + base) = make_uint4(ph0, ph1, ph2, ph3);
            *(uint4*)(xlo[buf ^ 1] + base) = make_uint4(pl0, pl1, pl2, pl3);
        }

#pragma unroll
        for (int ksl = 0; ksl < 2; ksl++) {
            int ks = kc * 2 + ksl;
            int r = rg * 16 + grp;
            int cb = ksl * 8;
            unsigned ah[4], al[4];
            ah[0] = xhi[buf][r * XS2 + cb + qid];
            ah[1] = xhi[buf][(r + 8) * XS2 + cb + qid];
            ah[2] = xhi[buf][r * XS2 + cb + qid + 4];
            ah[3] = xhi[buf][(r + 8) * XS2 + cb + qid + 4];
            al[0] = xlo[buf][r * XS2 + cb + qid];
            al[1] = xlo[buf][(r + 8) * XS2 + cb + qid];
            al[2] = xlo[buf][r * XS2 + cb + qid + 4];
            al[3] = xlo[buf][(r + 8) * XS2 + cb + qid + 4];
#pragma unroll
            for (int t = 0; t < 4; t++) {
                int tt = cg * 4 + t;
                uint4 w = __ldg(&g_wfrag[(ks * 8 + tt) * 32 + lane]);
                mma_bf16(d[t], ah, w.x, w.y);
                mma_bf16(d[t], al, w.x, w.y);
                mma_bf16(d[t], ah, w.z, w.w);
            }
        }
    }

    // epilogue: UNscaled h1 (dinv applied during aggregation)
    int r0 = node0 + rg * 16 + grp;
#pragma unroll
    for (int t = 0; t < 4; t++) {
        int col = cg * 32 + t * 8 + qid * 2;
        if (r0 < n)     *(float2*)(g_h1 + (size_t)r0 * 64 + col)       = make_float2(d[t][0], d[t][1]);
        if (r0 + 8 < n) *(float2*)(g_h1 + (size_t)(r0 + 8) * 64 + col) = make_float2(d[t][2], d[t][3]);
    }
}

// ---- layer 1 agg: a1 = relu(dinv_d*(sum dinv_s*h1_s + dinv_d*h1_d) + b1) -----
// Per-neighbor dinv gathered as lane-uniform scalar loads; ADD becomes FMA.
__global__ __launch_bounds__(256) void k_agg1(const float* __restrict__ b1, int n) {
    int lane = threadIdx.x & 31;
    int node = (blockIdx.x * blockDim.x + threadIdx.x) >> 5;
    if (node >= n) return;

    float di = g_dinv[node];
    float2 vs = ((const float2*)(g_h1 + (size_t)node * 64))[lane];  // self row
    float2 acc0 = make_float2(di * vs.x, di * vs.y);
    float2 acc1 = make_float2(0.f, 0.f);
    float2 acc2 = make_float2(0.f, 0.f);
    float2 acc3 = make_float2(0.f, 0.f);

    const int* ep = g_srcfix + (size_t)node * DEGMAX;
    int cnt = g_cnt[node];
    if (cnt > DEGMAX) cnt = DEGMAX;
    int k = 0;
    for (; k + 8 <= cnt; k += 8) {
        int4 sa = *(const int4*)(ep + k);
        int4 sb = *(const int4*)(ep + k + 4);
        float w0 = g_dinv[sa.x], w1 = g_dinv[sa.y], w2 = g_dinv[sa.z], w3 = g_dinv[sa.w];
        float w4 = g_dinv[sb.x], w5 = g_dinv[sb.y], w6 = g_dinv[sb.z], w7 = g_dinv[sb.w];
        float2 v0 = ((const float2*)(g_h1 + (size_t)sa.x * 64))[lane];
        float2 v1 = ((const float2*)(g_h1 + (size_t)sa.y * 64))[lane];
        float2 v2 = ((const float2*)(g_h1 + (size_t)sa.z * 64))[lane];
        float2 v3 = ((const float2*)(g_h1 + (size_t)sa.w * 64))[lane];
        float2 v4 = ((const float2*)(g_h1 + (size_t)sb.x * 64))[lane];
        float2 v5 = ((const float2*)(g_h1 + (size_t)sb.y * 64))[lane];
        float2 v6 = ((const float2*)(g_h1 + (size_t)sb.z * 64))[lane];
        float2 v7 = ((const float2*)(g_h1 + (size_t)sb.w * 64))[lane];
        acc0.x = fmaf(w0, v0.x, acc0.x); acc0.y = fmaf(w0, v0.y, acc0.y);
        acc1.x = fmaf(w1, v1.x, acc1.x); acc1.y = fmaf(w1, v1.y, acc1.y);
        acc2.x = fmaf(w2, v2.x, acc2.x); acc2.y = fmaf(w2, v2.y, acc2.y);
        acc3.x = fmaf(w3, v3.x, acc3.x); acc3.y = fmaf(w3, v3.y, acc3.y);
        acc0.x = fmaf(w4, v4.x, acc0.x); acc0.y = fmaf(w4, v4.y, acc0.y);
        acc1.x = fmaf(w5, v5.x, acc1.x); acc1.y = fmaf(w5, v5.y, acc1.y);
        acc2.x = fmaf(w6, v6.x, acc2.x); acc2.y = fmaf(w6, v6.y, acc2.y);
        acc3.x = fmaf(w7, v7.x, acc3.x); acc3.y = fmaf(w7, v7.y, acc3.y);
    }
    for (; k < cnt; k++) {
        int s = ep[k];
        float w = g_dinv[s];
        float2 v = ((const float2*)(g_h1 + (size_t)s * 64))[lane];
        acc0.x = fmaf(w, v.x, acc0.x);
        acc0.y = fmaf(w, v.y, acc0.y);
    }
    acc0.x += acc1.x + acc2.x + acc3.x;
    acc0.y += acc1.y + acc2.y + acc3.y;

    float2 bb = ((const float2*)b1)[lane];
    float ax = fmaxf(fmaf(di, acc0.x, bb.x), 0.f);
    float ay = fmaxf(fmaf(di, acc0.y, bb.y), 0.f);

    __nv_bfloat16 hx, lx, hy, ly;
    split_bf16(ax, hx, lx);
    split_bf16(ay, hy, ly);
    g_a1h[(size_t)node * 32 + lane] = pack_bf16(hx, hy);
    g_a1l[(size_t)node * 32 + lane] = pack_bf16(lx, ly);
}

// ---- layer 2 GEMM (tensor): ht2 = dinv * (a1 @ W2), A-frags direct from gmem --
__global__ __launch_bounds__(256) void k_gemm2t(int n) {
    int tid = threadIdx.x, lane = tid & 31, warp = tid >> 5;
    int node0 = blockIdx.x * 128;
    int grp = lane >> 2, qid = lane & 3;
    int r0 = node0 + warp * 16 + grp;

    float d[4][4];
#pragma unroll
    for (int t = 0; t < 4; t++) { d[t][0] = d[t][1] = d[t][2] = d[t][3] = 0.f; }

    const unsigned* ah_base0 = g_a1h + (size_t)r0 * 32;
    const unsigned* ah_base1 = g_a1h + (size_t)(r0 + 8) * 32;
    const unsigned* al_base0 = g_a1l + (size_t)r0 * 32;
    const unsigned* al_base1 = g_a1l + (size_t)(r0 + 8) * 32;

#pragma unroll
    for (int ks = 0; ks < 4; ks++) {
        unsigned ah[4], al[4];
        ah[0] = __ldg(ah_base0 + ks * 8 + qid);
        ah[1] = __ldg(ah_base1 + ks * 8 + qid);
        ah[2] = __ldg(ah_base0 + ks * 8 + qid + 4);
        ah[3] = __ldg(ah_base1 + ks * 8 + qid + 4);
        al[0] = __ldg(al_base0 + ks * 8 + qid);
        al[1] = __ldg(al_base1 + ks * 8 + qid);
        al[2] = __ldg(al_base0 + ks * 8 + qid + 4);
        al[3] = __ldg(al_base1 + ks * 8 + qid + 4);
#pragma unroll
        for (int t = 0; t < 4; t++) {
            uint4 w = __ldg(&g_w2frag[(ks * 4 + t) * 32 + lane]);
            mma_bf16(d[t], ah, w.x, w.y);
            mma_bf16(d[t], al, w.x, w.y);
            mma_bf16(d[t], ah, w.z, w.w);
        }
    }

    float di0 = (r0 < n)     ? g_dinv[r0]     : 0.f;
    float di1 = (r0 + 8 < n) ? g_dinv[r0 + 8] : 0.f;
#pragma unroll
    for (int t = 0; t < 4; t++) {
        int col = t * 8 + qid * 2;
        if (r0 < n)     *(float2*)(g_h2 + (size_t)r0 * 32 + col)       = make_float2(di0 * d[t][0], di0 * d[t][1]);
        if (r0 + 8 < n) *(float2*)(g_h2 + (size_t)(r0 + 8) * 32 + col) = make_float2(di1 * d[t][2], di1 * d[t][3]);
    }
}

// ------- layer 2 agg fused with final linear ------------------------------------
__global__ __launch_bounds__(256) void k_agg2(const float* __restrict__ b2,
                                              const float* __restrict__ Wlin,
                                              const float* __restrict__ blin,
                                              float* __restrict__ out, int n) {
    int lane = threadIdx.x & 31;
    int node = (blockIdx.x * blockDim.x + threadIdx.x) >> 5;
    if (node >= n) return;

    float di = g_dinv[node];
    float acc0 = g_h2[(size_t)node * 32 + lane];   // self loop (pre-scaled ht2)
    float acc1 = 0.f, acc2 = 0.f, acc3 = 0.f;

    const int* ep = g_srcfix + (size_t)node * DEGMAX;
    int cnt = g_cnt[node];
    if (cnt > DEGMAX) cnt = DEGMAX;
    int k = 0;
    for (; k + 16 <= cnt; k += 16) {
        int4 sa = *(const int4*)(ep + k);
        int4 sb = *(const int4*)(ep + k + 4);
        int4 sc = *(const int4*)(ep + k + 8);
        int4 sd = *(const int4*)(ep + k + 12);
        float v0  = g_h2[(size_t)sa.x * 32 + lane];
        float v1  = g_h2[(size_t)sa.y * 32 + lane];
        float v2  = g_h2[(size_t)sa.z * 32 + lane];
        float v3  = g_h2[(size_t)sa.w * 32 + lane];
        float v4  = g_h2[(size_t)sb.x * 32 + lane];
        float v5  = g_h2[(size_t)sb.y * 32 + lane];
        float v6  = g_h2[(size_t)sb.z * 32 + lane];
        float v7  = g_h2[(size_t)sb.w * 32 + lane];
        float v8  = g_h2[(size_t)sc.x * 32 + lane];
        float v9  = g_h2[(size_t)sc.y * 32 + lane];
        float v10 = g_h2[(size_t)sc.z * 32 + lane];
        float v11 = g_h2[(size_t)sc.w * 32 + lane];
        float v12 = g_h2[(size_t)sd.x * 32 + lane];
        float v13 = g_h2[(size_t)sd.y * 32 + lane];
        float v14 = g_h2[(size_t)sd.z * 32 + lane];
        float v15 = g_h2[(size_t)sd.w * 32 + lane];
        acc0 += v0 + v4 + v8  + v12;
        acc1 += v1 + v5 + v9  + v13;
        acc2 += v2 + v6 + v10 + v14;
        acc3 += v3 + v7 + v11 + v15;
    }
    for (; k + 8 <= cnt; k += 8) {
        int4 sa = *(const int4*)(ep + k);
        int4 sb = *(const int4*)(ep + k + 4);
        float v0 = g_h2[(size_t)sa.x * 32 + lane];
        float v1 = g_h2[(size_t)sa.y * 32 + lane];
        float v2 = g_h2[(size_t)sa.z * 32 + lane];
        float v3 = g_h2[(size_t)sa.w * 32 + lane];
        float v4 = g_h2[(size_t)sb.x * 32 + lane];
        float v5 = g_h2[(size_t)sb.y * 32 + lane];
        float v6 = g_h2[(size_t)sb.z * 32 + lane];
        float v7 = g_h2[(size_t)sb.w * 32 + lane];
        acc0 += v0 + v4; acc1 += v1 + v5; acc2 += v2 + v6; acc3 += v3 + v7;
    }
    for (; k < cnt; k++) {
        acc0 += g_h2[(size_t)ep[k] * 32 + lane];
    }
    acc0 += acc1 + acc2 + acc3;

    float v = fmaxf(fmaf(di, acc0, b2[lane]), 0.f);
    float p = v * Wlin[lane];
#pragma unroll
    for (int off = 16; off > 0; off >>= 1) p += __shfl_xor_sync(0xffffffffu, p, off);
    if (lane == 0) out[node] = p + blin[0];
}

// ---------------- launch -------------------------------------------------------
extern "C" void kernel_launch(void* const* d_in, const int* in_sizes, int n_in,
                              void* d_out, int out_size) {
    const float* x    = (const float*)d_in[0];
    const int*   ei   = (const int*)  d_in[1];
    const float* W1   = (const float*)d_in[2];
    const float* b1   = (const float*)d_in[3];
    const float* W2   = (const float*)d_in[4];
    const float* b2   = (const float*)d_in[5];
    const float* Wlin = (const float*)d_in[6];
    const float* blin = (const float*)d_in[7];
    float* out = (float*)d_out;

    int n = in_sizes[0] / 256;
    int e = in_sizes[1] / 2;
    if (n > NMAX) n = NMAX;
    if (e > EMAX) e = EMAX;
    const int* src = ei;
    const int* dst = ei + e;

    void* cnt_ptr = nullptr;
    cudaGetSymbolAddress(&cnt_ptr, g_cnt);
    cudaMemsetAsync(cnt_ptr, 0, (size_t)n * sizeof(int));

    int g1 = (n + 63) / 64;
    int fb = (e + 255) / 256;

    // ncu window captures kernel slot 4 = k_agg1 (verify dinv-gather tax)
    k_prepw  <<<16, 256>>>(W1, W2);
    k_mega   <<<g1 + fb, 256>>>(x, n, src, dst, e, g1);
    k_dinv   <<<(n + 255) / 256, 256>>>(n);
    k_agg1   <<<(n + 7) / 8, 256>>>(b1, n);
    k_gemm2t <<<(n + 127) / 128, 256>>>(n);
    k_agg2   <<<(n + 7) / 8, 256>>>(b2, Wlin, blin, out, n);
}

// round 14
// speedup vs baseline: 1.0710x; 1.0710x over previous
#include <cuda_runtime.h>
#include <cuda_bf16.h>

#define NMAX 100000
#define NPAD 100128          // NMAX rounded up to 128-row block
#define EMAX 1600000
#define DEGMAX 64

// ---------------- scratch (device globals) -----------------------------------
__device__ int      g_cnt[NMAX];
__device__ float    g_dinv[NMAX];
__device__ int      g_srcfix[(size_t)NMAX * DEGMAX];  // per-dst src lists
__device__ float    g_h1[(size_t)NPAD * 64];          // dinv-scaled layer1 features
__device__ unsigned g_a1h[(size_t)NPAD * 32];         // a1 bf16-hi packed pairs
__device__ unsigned g_a1l[(size_t)NPAD * 32];         // a1 bf16-lo packed pairs
__device__ float    g_h2[(size_t)NPAD * 32];          // dinv-scaled layer2 features
__device__ uint4    g_wfrag[4096];                    // W1 bf16 fragments
__device__ uint4    g_w2frag[512];                    // W2 bf16 fragments

// ---------------- bf16 helpers -------------------------------------------------
__device__ __forceinline__ unsigned pack_bf16(__nv_bfloat16 lo, __nv_bfloat16 hi) {
    __nv_bfloat162 p; p.x = lo; p.y = hi;
    return *(unsigned*)&p;
}
__device__ __forceinline__ void split_bf16(float f, __nv_bfloat16& h, __nv_bfloat16& l) {
    h = __float2bfloat16_rn(f);
    l = __float2bfloat16_rn(f - __bfloat162float(h));
}
__device__ __forceinline__ void mma_bf16(float* d, const unsigned* a, unsigned b0, unsigned b1) {
    asm volatile(
        "mma.sync.aligned.m16n8k16.row.col.f32.bf16.bf16.f32 "
        "{%0,%1,%2,%3}, {%4,%5,%6,%7}, {%8,%9}, {%0,%1,%2,%3};"
        : "+f"(d[0]), "+f"(d[1]), "+f"(d[2]), "+f"(d[3])
        : "r"(a[0]), "r"(a[1]), "r"(a[2]), "r"(a[3]), "r"(b0), "r"(b1));
}

// ---- build: bucket-fill src lists ----------------------------------------------
__global__ void k_fill(const int* __restrict__ src, const int* __restrict__ dst, int e) {
    int i = blockIdx.x * blockDim.x + threadIdx.x;
    if (i < e) {
        int s = src[i], d = dst[i];
        int pos = atomicAdd(&g_cnt[d], 1);
        if (pos < DEGMAX) g_srcfix[(size_t)d * DEGMAX + pos] = s;
    }
}

// ---- prep: W1/W2 bf16 hi/lo fragments (validated layouts) ----------------------
__global__ void k_prepw(const float* __restrict__ W1, const float* __restrict__ W2) {
    int i = blockIdx.x * blockDim.x + threadIdx.x;
    if (i < 4096) {   // W1 fragments
        int lane = i & 31;
        int t    = (i >> 5) & 7;
        int ks   = i >> 8;
        int qid = lane & 3, grp = lane >> 2;
        int col = t * 8 + grp;
        int k0 = ks * 16 + qid * 2;
        float f00 = W1[k0 * 64 + col],       f01 = W1[(k0 + 1) * 64 + col];
        float f10 = W1[(k0 + 8) * 64 + col], f11 = W1[(k0 + 9) * 64 + col];
        __nv_bfloat16 h00, l00, h01, l01, h10, l10, h11, l11;
        split_bf16(f00, h00, l00); split_bf16(f01, h01, l01);
        split_bf16(f10, h10, l10); split_bf16(f11, h11, l11);
        g_wfrag[i] = make_uint4(pack_bf16(h00, h01), pack_bf16(h10, h11),
                                pack_bf16(l00, l01), pack_bf16(l10, l11));
    }
    if (i < 512) {    // W2 fragments
        int lane = i & 31;
        int t    = (i >> 5) & 3;
        int ks   = i >> 7;
        int qid = lane & 3, grp = lane >> 2;
        int col = t * 8 + grp;
        int k0 = ks * 16 + qid * 2;
        float f00 = W2[k0 * 32 + col],       f01 = W2[(k0 + 1) * 32 + col];
        float f10 = W2[(k0 + 8) * 32 + col], f11 = W2[(k0 + 9) * 32 + col];
        __nv_bfloat16 h00, l00, h01, l01, h10, l10, h11, l11;
        split_bf16(f00, h00, l00); split_bf16(f01, h01, l01);
        split_bf16(f10, h10, l10); split_bf16(f11, h11, l11);
        g_w2frag[i] = make_uint4(pack_bf16(h00, h01), pack_bf16(h10, h11),
                                 pack_bf16(l00, l01), pack_bf16(l10, l11));
    }
}

__global__ void k_dinv(int n) {
    int i = blockIdx.x * blockDim.x + threadIdx.x;
    if (i < n) g_dinv[i] = rsqrtf((float)(g_cnt[i] + 1));  // +1 self loop
}

// ------- layer 1 GEMM: ht1 = dinv * (x @ W1), bf16x3 m16n8k16 -----------------
// R10 geometry (proven best): block 64 rows, warp tile 16 rows x 32 cols,
// single-buffer inline-split staging. NEW: __launch_bounds__(256, 4) caps regs
// at 64 -> 4 CTAs/SM (was reg-limited to 3 at 68-70 regs; occ 35% -> ~50%).
#define XS2 20
__global__ __launch_bounds__(256, 4) void k_gemm1(const float* __restrict__ x, int n) {
    __shared__ unsigned xhi[64 * XS2];
    __shared__ unsigned xlo[64 * XS2];
    int tid = threadIdx.x, lane = tid & 31, warp = tid >> 5;
    int node0 = blockIdx.x * 64;
    int grp = lane >> 2, qid = lane & 3;
    int rg = warp >> 1, cg = warp & 1;

    float d[4][4];
#pragma unroll
    for (int t = 0; t < 4; t++) { d[t][0] = d[t][1] = d[t][2] = d[t][3] = 0.f; }

    int srow = tid >> 2;          // staging: row 0..63
    int sq   = tid & 3;           // k-quarter: 8 consecutive k values

    for (int kc = 0; kc < 8; kc++) {            // K chunk of 32
        __syncthreads();
        {
            float4 v0 = make_float4(0.f, 0.f, 0.f, 0.f);
            float4 v1 = make_float4(0.f, 0.f, 0.f, 0.f);
            if (node0 + srow < n) {
                const float4* xp = (const float4*)(x + (size_t)(node0 + srow) * 256 + kc * 32 + sq * 8);
                v0 = xp[0]; v1 = xp[1];
            }
            __nv_bfloat16 h0, l0, h1, l1;
            unsigned ph0, ph1, ph2, ph3, pl0, pl1, pl2, pl3;
            split_bf16(v0.x, h0, l0); split_bf16(v0.y, h1, l1);
            ph0 = pack_bf16(h0, h1); pl0 = pack_bf16(l0, l1);
            split_bf16(v0.z, h0, l0); split_bf16(v0.w, h1, l1);
            ph1 = pack_bf16(h0, h1); pl1 = pack_bf16(l0, l1);
            split_bf16(v1.x, h0, l0); split_bf16(v1.y, h1, l1);
            ph2 = pack_bf16(h0, h1); pl2 = pack_bf16(l0, l1);
            split_bf16(v1.z, h0, l0); split_bf16(v1.w, h1, l1);
            ph3 = pack_bf16(h0, h1); pl3 = pack_bf16(l0, l1);
            unsigned base = srow * XS2 + sq * 4;
            *(uint4*)(xhi + base) = make_uint4(ph0, ph1, ph2, ph3);
            *(uint4*)(xlo + base) = make_uint4(pl0, pl1, pl2, pl3);
        }
        __syncthreads();

#pragma unroll
        for (int ksl = 0; ksl < 2; ksl++) {
            int ks = kc * 2 + ksl;
            int r = rg * 16 + grp;
            int cb = ksl * 8;
            unsigned ah[4], al[4];
            ah[0] = xhi[r * XS2 + cb + qid];
            ah[1] = xhi[(r + 8) * XS2 + cb + qid];
            ah[2] = xhi[r * XS2 + cb + qid + 4];
            ah[3] = xhi[(r + 8) * XS2 + cb + qid + 4];
            al[0] = xlo[r * XS2 + cb + qid];
            al[1] = xlo[(r + 8) * XS2 + cb + qid];
            al[2] = xlo[r * XS2 + cb + qid + 4];
            al[3] = xlo[(r + 8) * XS2 + cb + qid + 4];
#pragma unroll
            for (int t = 0; t < 4; t++) {
                int tt = cg * 4 + t;
                uint4 w = __ldg(&g_wfrag[(ks * 8 + tt) * 32 + lane]);
                mma_bf16(d[t], ah, w.x, w.y);
                mma_bf16(d[t], al, w.x, w.y);
                mma_bf16(d[t], ah, w.z, w.w);
            }
        }
    }

    int r0 = node0 + rg * 16 + grp;
    float di0 = (r0 < n)     ? g_dinv[r0]     : 0.f;
    float di1 = (r0 + 8 < n) ? g_dinv[r0 + 8] : 0.f;
#pragma unroll
    for (int t = 0; t < 4; t++) {
        int col = cg * 32 + t * 8 + qid * 2;
        if (r0 < n)     *(float2*)(g_h1 + (size_t)r0 * 64 + col)       = make_float2(di0 * d[t][0], di0 * d[t][1]);
        if (r0 + 8 < n) *(float2*)(g_h1 + (size_t)(r0 + 8) * 64 + col) = make_float2(di1 * d[t][2], di1 * d[t][3]);
    }
}

// ---- layer 1 aggregation: a1 = relu(dinv*(sum ht1) + b1), stored packed bf16 --
// MLP=16 main loop (proven R10 form).
__global__ __launch_bounds__(256) void k_agg1(const float* __restrict__ b1, int n) {
    int lane = threadIdx.x & 31;
    int node = (blockIdx.x * blockDim.x + threadIdx.x) >> 5;
    if (node >= n) return;

    float di = g_dinv[node];
    float2 acc0 = ((const float2*)(g_h1 + (size_t)node * 64))[lane];  // self loop
    float2 acc1 = make_float2(0.f, 0.f);
    float2 acc2 = make_float2(0.f, 0.f);
    float2 acc3 = make_float2(0.f, 0.f);

    const int* ep = g_srcfix + (size_t)node * DEGMAX;
    int cnt = g_cnt[node];
    if (cnt > DEGMAX) cnt = DEGMAX;
    int k = 0;
    for (; k + 16 <= cnt; k += 16) {
        int4 sa = *(const int4*)(ep + k);
        int4 sb = *(const int4*)(ep + k + 4);
        int4 sc = *(const int4*)(ep + k + 8);
        int4 sd = *(const int4*)(ep + k + 12);
        float2 v0  = ((const float2*)(g_h1 + (size_t)sa.x * 64))[lane];
        float2 v1  = ((const float2*)(g_h1 + (size_t)sa.y * 64))[lane];
        float2 v2  = ((const float2*)(g_h1 + (size_t)sa.z * 64))[lane];
        float2 v3  = ((const float2*)(g_h1 + (size_t)sa.w * 64))[lane];
        float2 v4  = ((const float2*)(g_h1 + (size_t)sb.x * 64))[lane];
        float2 v5  = ((const float2*)(g_h1 + (size_t)sb.y * 64))[lane];
        float2 v6  = ((const float2*)(g_h1 + (size_t)sb.z * 64))[lane];
        float2 v7  = ((const float2*)(g_h1 + (size_t)sb.w * 64))[lane];
        float2 v8  = ((const float2*)(g_h1 + (size_t)sc.x * 64))[lane];
        float2 v9  = ((const float2*)(g_h1 + (size_t)sc.y * 64))[lane];
        float2 v10 = ((const float2*)(g_h1 + (size_t)sc.z * 64))[lane];
        float2 v11 = ((const float2*)(g_h1 + (size_t)sc.w * 64))[lane];
        float2 v12 = ((const float2*)(g_h1 + (size_t)sd.x * 64))[lane];
        float2 v13 = ((const float2*)(g_h1 + (size_t)sd.y * 64))[lane];
        float2 v14 = ((const float2*)(g_h1 + (size_t)sd.z * 64))[lane];
        float2 v15 = ((const float2*)(g_h1 + (size_t)sd.w * 64))[lane];
        acc0.x += v0.x  + v4.x;  acc0.y += v0.y  + v4.y;
        acc1.x += v1.x  + v5.x;  acc1.y += v1.y  + v5.y;
        acc2.x += v2.x  + v6.x;  acc2.y += v2.y  + v6.y;
        acc3.x += v3.x  + v7.x;  acc3.y += v3.y  + v7.y;
        acc0.x += v8.x  + v12.x; acc0.y += v8.y  + v12.y;
        acc1.x += v9.x  + v13.x; acc1.y += v9.y  + v13.y;
        acc2.x += v10.x + v14.x; acc2.y += v10.y + v14.y;
        acc3.x += v11.x + v15.x; acc3.y += v11.y + v15.y;
    }
    for (; k + 8 <= cnt; k += 8) {
        int4 sa = *(const int4*)(ep + k);
        int4 sb = *(const int4*)(ep + k + 4);
        float2 v0 = ((const float2*)(g_h1 + (size_t)sa.x * 64))[lane];
        float2 v1 = ((const float2*)(g_h1 + (size_t)sa.y * 64))[lane];
        float2 v2 = ((const float2*)(g_h1 + (size_t)sa.z * 64))[lane];
        float2 v3 = ((const float2*)(g_h1 + (size_t)sa.w * 64))[lane];
        float2 v4 = ((const float2*)(g_h1 + (size_t)sb.x * 64))[lane];
        float2 v5 = ((const float2*)(g_h1 + (size_t)sb.y * 64))[lane];
        float2 v6 = ((const float2*)(g_h1 + (size_t)sb.z * 64))[lane];
        float2 v7 = ((const float2*)(g_h1 + (size_t)sb.w * 64))[lane];
        acc0.x += v0.x + v4.x; acc0.y += v0.y + v4.y;
        acc1.x += v1.x + v5.x; acc1.y += v1.y + v5.y;
        acc2.x += v2.x + v6.x; acc2.y += v2.y + v6.y;
        acc3.x += v3.x + v7.x; acc3.y += v3.y + v7.y;
    }
    for (; k < cnt; k++) {
        int s = ep[k];
        float2 v = ((const float2*)(g_h1 + (size_t)s * 64))[lane];
        acc0.x += v.x; acc0.y += v.y;
    }
    acc0.x += acc1.x + acc2.x + acc3.x;
    acc0.y += acc1.y + acc2.y + acc3.y;

    float2 bb = ((const float2*)b1)[lane];
    float ax = fmaxf(fmaf(di, acc0.x, bb.x), 0.f);
    float ay = fmaxf(fmaf(di, acc0.y, bb.y), 0.f);

    __nv_bfloat16 hx, lx, hy, ly;
    split_bf16(ax, hx, lx);
    split_bf16(ay, hy, ly);
    g_a1h[(size_t)node * 32 + lane] = pack_bf16(hx, hy);
    g_a1l[(size_t)node * 32 + lane] = pack_bf16(lx, ly);
}

// ---- layer 2 GEMM (tensor): ht2 = dinv * (a1 @ W2), A-frags direct from gmem --
__global__ __launch_bounds__(256) void k_gemm2t(int n) {
    int tid = threadIdx.x, lane = tid & 31, warp = tid >> 5;
    int node0 = blockIdx.x * 128;
    int grp = lane >> 2, qid = lane & 3;
    int r0 = node0 + warp * 16 + grp;

    float d[4][4];
#pragma unroll
    for (int t = 0; t < 4; t++) { d[t][0] = d[t][1] = d[t][2] = d[t][3] = 0.f; }

    const unsigned* ah_base0 = g_a1h + (size_t)r0 * 32;
    const unsigned* ah_base1 = g_a1h + (size_t)(r0 + 8) * 32;
    const unsigned* al_base0 = g_a1l + (size_t)r0 * 32;
    const unsigned* al_base1 = g_a1l + (size_t)(r0 + 8) * 32;

#pragma unroll
    for (int ks = 0; ks < 4; ks++) {
        unsigned ah[4], al[4];
        ah[0] = __ldg(ah_base0 + ks * 8 + qid);
        ah[1] = __ldg(ah_base1 + ks * 8 + qid);
        ah[2] = __ldg(ah_base0 + ks * 8 + qid + 4);
        ah[3] = __ldg(ah_base1 + ks * 8 + qid + 4);
        al[0] = __ldg(al_base0 + ks * 8 + qid);
        al[1] = __ldg(al_base1 + ks * 8 + qid);
        al[2] = __ldg(al_base0 + ks * 8 + qid + 4);
        al[3] = __ldg(al_base1 + ks * 8 + qid + 4);
#pragma unroll
        for (int t = 0; t < 4; t++) {
            uint4 w = __ldg(&g_w2frag[(ks * 4 + t) * 32 + lane]);
            mma_bf16(d[t], ah, w.x, w.y);
            mma_bf16(d[t], al, w.x, w.y);
            mma_bf16(d[t], ah, w.z, w.w);
        }
    }

    float di0 = (r0 < n)     ? g_dinv[r0]     : 0.f;
    float di1 = (r0 + 8 < n) ? g_dinv[r0 + 8] : 0.f;
#pragma unroll
    for (int t = 0; t < 4; t++) {
        int col = t * 8 + qid * 2;
        if (r0 < n)     *(float2*)(g_h2 + (size_t)r0 * 32 + col)       = make_float2(di0 * d[t][0], di0 * d[t][1]);
        if (r0 + 8 < n) *(float2*)(g_h2 + (size_t)(r0 + 8) * 32 + col) = make_float2(di1 * d[t][2], di1 * d[t][3]);
    }
}

// ------- layer 2 agg fused with final linear ------------------------------------
__global__ __launch_bounds__(256) void k_agg2(const float* __restrict__ b2,
                                              const float* __restrict__ Wlin,
                                              const float* __restrict__ blin,
                                              float* __restrict__ out, int n) {
    int lane = threadIdx.x & 31;
    int node = (blockIdx.x * blockDim.x + threadIdx.x) >> 5;
    if (node >= n) return;

    float di = g_dinv[node];
    float acc0 = g_h2[(size_t)node * 32 + lane];   // self loop
    float acc1 = 0.f, acc2 = 0.f, acc3 = 0.f;

    const int* ep = g_srcfix + (size_t)node * DEGMAX;
    int cnt = g_cnt[node];
    if (cnt > DEGMAX) cnt = DEGMAX;
    int k = 0;
    for (; k + 16 <= cnt; k += 16) {
        int4 sa = *(const int4*)(ep + k);
        int4 sb = *(const int4*)(ep + k + 4);
        int4 sc = *(const int4*)(ep + k + 8);
        int4 sd = *(const int4*)(ep + k + 12);
        float v0  = g_h2[(size_t)sa.x * 32 + lane];
        float v1  = g_h2[(size_t)sa.y * 32 + lane];
        float v2  = g_h2[(size_t)sa.z * 32 + lane];
        float v3  = g_h2[(size_t)sa.w * 32 + lane];
        float v4  = g_h2[(size_t)sb.x * 32 + lane];
        float v5  = g_h2[(size_t)sb.y * 32 + lane];
        float v6  = g_h2[(size_t)sb.z * 32 + lane];
        float v7  = g_h2[(size_t)sb.w * 32 + lane];
        float v8  = g_h2[(size_t)sc.x * 32 + lane];
        float v9  = g_h2[(size_t)sc.y * 32 + lane];
        float v10 = g_h2[(size_t)sc.z * 32 + lane];
        float v11 = g_h2[(size_t)sc.w * 32 + lane];
        float v12 = g_h2[(size_t)sd.x * 32 + lane];
        float v13 = g_h2[(size_t)sd.y * 32 + lane];
        float v14 = g_h2[(size_t)sd.z * 32 + lane];
        float v15 = g_h2[(size_t)sd.w * 32 + lane];
        acc0 += v0 + v4 + v8  + v12;
        acc1 += v1 + v5 + v9  + v13;
        acc2 += v2 + v6 + v10 + v14;
        acc3 += v3 + v7 + v11 + v15;
    }
    for (; k + 8 <= cnt; k += 8) {
        int4 sa = *(const int4*)(ep + k);
        int4 sb = *(const int4*)(ep + k + 4);
        float v0 = g_h2[(size_t)sa.x * 32 + lane];
        float v1 = g_h2[(size_t)sa.y * 32 + lane];
        float v2 = g_h2[(size_t)sa.z * 32 + lane];
        float v3 = g_h2[(size_t)sa.w * 32 + lane];
        float v4 = g_h2[(size_t)sb.x * 32 + lane];
        float v5 = g_h2[(size_t)sb.y * 32 + lane];
        float v6 = g_h2[(size_t)sb.z * 32 + lane];
        float v7 = g_h2[(size_t)sb.w * 32 + lane];
        acc0 += v0 + v4; acc1 += v1 + v5; acc2 += v2 + v6; acc3 += v3 + v7;
    }
    for (; k < cnt; k++) {
        acc0 += g_h2[(size_t)ep[k] * 32 + lane];
    }
    acc0 += acc1 + acc2 + acc3;

    float v = fmaxf(fmaf(di, acc0, b2[lane]), 0.f);
    float p = v * Wlin[lane];
#pragma unroll
    for (int off = 16; off > 0; off >>= 1) p += __shfl_xor_sync(0xffffffffu, p, off);
    if (lane == 0) out[node] = p + blin[0];
}

// ---------------- launch -------------------------------------------------------
extern "C" void kernel_launch(void* const* d_in, const int* in_sizes, int n_in,
                              void* d_out, int out_size) {
    const float* x    = (const float*)d_in[0];
    const int*   ei   = (const int*)  d_in[1];
    const float* W1   = (const float*)d_in[2];
    const float* b1   = (const float*)d_in[3];
    const float* W2   = (const float*)d_in[4];
    const float* b2   = (const float*)d_in[5];
    const float* Wlin = (const float*)d_in[6];
    const float* blin = (const float*)d_in[7];
    float* out = (float*)d_out;

    int n = in_sizes[0] / 256;
    int e = in_sizes[1] / 2;
    if (n > NMAX) n = NMAX;
    if (e > EMAX) e = EMAX;
    const int* src = ei;
    const int* dst = ei + e;

    void* cnt_ptr = nullptr;
    cudaGetSymbolAddress(&cnt_ptr, g_cnt);
    cudaMemsetAsync(cnt_ptr, 0, (size_t)n * sizeof(int));

    // ncu window captures kernel slot 4 = k_gemm1 (verify reg/occupancy fix)
    k_fill   <<<(e + 255) / 256, 256>>>(src, dst, e);
    k_prepw  <<<16, 256>>>(W1, W2);
    k_dinv   <<<(n + 255) / 256, 256>>>(n);
    k_gemm1  <<<(n + 63) / 64, 256>>>(x, n);
    k_agg1   <<<(n + 7) / 8, 256>>>(b1, n);
    k_gemm2t <<<(n + 127) / 128, 256>>>(n);
    k_agg2   <<<(n + 7) / 8, 256>>>(b2, Wlin, blin, out, n);
}